// round 14
// baseline (speedup 1.0000x reference)
#include <cuda_runtime.h>
#include <cuda_fp16.h>
#include <cstdint>

// ---------------- problem constants ----------------
#define NB     32
#define CIN    256
#define COUT   32
#define CTOT   288
#define HH     56
#define WW     56
#define HW     3136
#define EPSV   1e-5f

// padded NHWC activation buffer: [n][py 58][px 58][c 256] fp16
// __device__ globals are zero-initialized; the pad border is NEVER written,
// so it stays zero across all replays (no border-zero kernel needed).
#define PW       58
#define PPITCH   (PW*256)        // 14848 halfs per padded row
#define NPITCH   (PW*PPITCH)     // 861184 halfs per image

__device__ __half g_act[(size_t)NB * NPITCH];   // 55.1 MB
__device__ __half g_wt[COUT * 2304];            // [oc][tap*256+c]

// ---------------- PTX helpers (baseline PTX only) ----------------
static __device__ __forceinline__ uint32_t smem_u32(const void* p) {
    uint32_t a;
    asm("{ .reg .u64 t; cvta.to.shared.u64 t, %1; cvt.u32.u64 %0, t; }"
        : "=r"(a) : "l"(p));
    return a;
}
static __device__ __forceinline__ void cp_async16(uint32_t dst, const void* src) {
    asm volatile("cp.async.cg.shared.global [%0], [%1], 16;"
                 :: "r"(dst), "l"(src) : "memory");
}
static __device__ __forceinline__ void ldsm_x4(uint32_t& r0, uint32_t& r1,
                                               uint32_t& r2, uint32_t& r3, uint32_t addr) {
    asm volatile("ldmatrix.sync.aligned.m8n8.x4.shared.b16 {%0,%1,%2,%3}, [%4];"
                 : "=r"(r0), "=r"(r1), "=r"(r2), "=r"(r3) : "r"(addr));
}
static __device__ __forceinline__ void mma16816(float* c, uint32_t a0, uint32_t a1,
                                                uint32_t a2, uint32_t a3,
                                                uint32_t b0, uint32_t b1) {
    asm volatile("mma.sync.aligned.m16n8k16.row.col.f32.f16.f16.f32 "
                 "{%0,%1,%2,%3}, {%4,%5,%6,%7}, {%8,%9}, {%0,%1,%2,%3};"
                 : "+f"(c[0]), "+f"(c[1]), "+f"(c[2]), "+f"(c[3])
                 : "r"(a0), "r"(a1), "r"(a2), "r"(a3), "r"(b0), "r"(b1));
}

// ---------------- kernel 1: stage1 (BN+ReLU + passthrough) with fused wtrans -----
// grid (49, 5, NB): cb<4 -> stage1 work; cb==4 -> weight-transform slice.
__global__ __launch_bounds__(256) void stage1_kernel(
    const float* __restrict__ in, const float* __restrict__ bw,
    const float* __restrict__ bb, const float* __restrict__ rm,
    const float* __restrict__ rv, const float* __restrict__ wsrc,
    float* __restrict__ out) {
    __shared__ __half st[64][72];     // [pixel][channel], 144B pitch
    __shared__ float ss[64], sh[64];

    int pb = blockIdx.x, cb = blockIdx.y, n = blockIdx.z;
    int tid = threadIdx.x;

    if (cb == 4) {
        // ---- weight transform OIHW -> [oc][tap*256+c] fp16 ----
        // 73728 elements over 49*NB blocks of 256 threads.
        int bi = blockIdx.z * 49 + pb;            // 0..1567
        int j = bi * 256 + tid;
        // strided so only the first 288 block-slots do work; rest exit
        if (j < COUT * 2304) {
            int oc = j / 2304;
            int k  = j % 2304;
            int t  = k >> 8;
            int c  = k & 255;
            g_wt[j] = __float2half(wsrc[(oc * CIN + c) * 9 + t]);
        }
        return;
    }

    if (tid < 64) {
        int c = cb * 64 + tid;
        float s = bw[c] * rsqrtf(rv[c] + EPSV);
        ss[tid] = s;
        sh[tid] = bb[c] - rm[c] * s;
    }
    __syncthreads();

    int ci0 = tid >> 4, pj = tid & 15;
    int p0 = pb * 64;
    #pragma unroll
    for (int r = 0; r < 4; r++) {
        int c = r * 16 + ci0;
        size_t off = ((size_t)n * CTOT + cb * 64 + c) * HW + p0;
        float4 v = ((const float4*)(in + off))[pj];
        ((float4*)(out + off))[pj] = v;                 // passthrough
        float s = ss[c], h = sh[c];
        st[pj * 4 + 0][c] = __float2half(fmaxf(fmaf(v.x, s, h), 0.f));
        st[pj * 4 + 1][c] = __float2half(fmaxf(fmaf(v.y, s, h), 0.f));
        st[pj * 4 + 2][c] = __float2half(fmaxf(fmaf(v.z, s, h), 0.f));
        st[pj * 4 + 3][c] = __float2half(fmaxf(fmaf(v.w, s, h), 0.f));
    }
    __syncthreads();

    #pragma unroll
    for (int r = 0; r < 2; r++) {
        int e = r * 256 + tid;
        int p = e >> 3, seg = e & 7;
        int P = p0 + p;
        int y = P / 56, x = P % 56;
        uint4 v = *(uint4*)&st[p][seg * 8];
        *(uint4*)(g_act + (size_t)n * NPITCH + (y + 1) * PPITCH + (x + 1) * 256
                  + cb * 64 + seg * 8) = v;
    }
}

// ---------------- kernel 2: implicit-GEMM conv, tap-reuse in smem ----------------
// (R10 configuration — best measured conv: M=256, 8 warps x m32n32, 2 CTAs/SM)
#define ABUF   23040             // 360 px slots x 64B (348 used + read slack)
#define BBUF   18432             // 9 taps x 32 oc x 32 ch x 2B
#define BOFF   (2*ABUF)          // 46080
#define CONV_SMEM (2*ABUF + 2*BBUF)  // 82944

__device__ __constant__ int TAPOFF[9] = {0,1,2, 58,59,60, 116,117,118};

static __device__ __forceinline__ void load_cg(int cg, int buf, uint32_t sb,
                                               const __half* actN, int y0, int tid) {
    uint32_t A = sb + buf * ABUF;
    const __half* asrc0 = actN + (size_t)y0 * PPITCH + cg * 32;
    #pragma unroll
    for (int it = 0; it < 6; it++) {
        int i = tid + it * 256;
        if (i < 1392) {                       // 348 pixels x 4 segs
            int p = i >> 2, seg = i & 3;
            int r = p / 58, px = p - r * 58;
            const void* src = asrc0 + r * PPITCH + px * 256 + seg * 8;
            uint32_t dst = A + (((uint32_t)p * 64) ^ ((uint32_t)seg << 4)
                                ^ (((uint32_t)(p & 7)) << 4));
            cp_async16(dst, src);
        }
    }
    uint32_t B = sb + BOFF + buf * BBUF;
    #pragma unroll
    for (int it = 0; it < 5; it++) {
        int i = tid + it * 256;
        if (i < 1152) {                       // 9 taps x 32 oc x 4 segs
            int tap = i >> 7, rem = i & 127;
            int oc = rem >> 2, seg = rem & 3;
            const void* src = g_wt + oc * 2304 + tap * 256 + cg * 32 + seg * 8;
            uint32_t dst = B + tap * 2048 + (((uint32_t)oc * 64) ^ ((uint32_t)seg << 4)
                                             ^ (((uint32_t)(oc & 7)) << 4));
            cp_async16(dst, src);
        }
    }
}

__global__ __launch_bounds__(256, 2)
void conv_kernel(float* __restrict__ out) {
    extern __shared__ __align__(128) char smem[];
    uint32_t sb = smem_u32(smem);
    int tid  = threadIdx.x;
    int w    = tid >> 5;                      // warp 0..7 -> m rows [w*32, w*32+32)
    int lane = tid & 31;
    int bx = blockIdx.x;
    int n  = bx / 14;
    int y0 = (bx % 14) * 4;                   // 4 output rows per CTA
    const __half* actN = g_act + (size_t)n * NPITCH;

    float acc[2][4][4];
    #pragma unroll
    for (int mt = 0; mt < 2; mt++)
        #pragma unroll
        for (int nb = 0; nb < 4; nb++)
            #pragma unroll
            for (int j = 0; j < 4; j++) acc[mt][nb][j] = 0.f;

    // per-lane fragment geometry
    int pb[2];
    #pragma unroll
    for (int mt = 0; mt < 2; mt++) {
        int m  = w * 32 + mt * 16 + (lane & 15);
        int yy = m >> 6, xx = m & 63;
        pb[mt] = yy * 58 + xx;
    }
    uint32_t aseg = (uint32_t)(lane >> 4);              // 0/1: k-half within k16
    int bn1 = ((lane >> 4) & 1) * 8 + (lane & 7);       // B rows n0-15
    int bn2 = bn1 + 16;                                 // B rows n16-31
    uint32_t bsw  = ((uint32_t)(lane & 7)) << 4;
    uint32_t bo1  = ((uint32_t)bn1 * 64) ^ bsw;
    uint32_t bo2  = ((uint32_t)bn2 * 64) ^ bsw;
    uint32_t bseg = (uint32_t)((lane >> 3) & 1);

    // prologue: two cg stages in flight
    load_cg(0, 0, sb, actN, y0, tid);
    asm volatile("cp.async.commit_group;" ::: "memory");
    load_cg(1, 1, sb, actN, y0, tid);
    asm volatile("cp.async.commit_group;" ::: "memory");

    for (int cg = 0; cg < 8; cg++) {
        asm volatile("cp.async.wait_group 1;" ::: "memory");
        __syncthreads();

        uint32_t A = sb + (cg & 1) * ABUF;
        uint32_t B = sb + BOFF + (cg & 1) * BBUF;

        #pragma unroll
        for (int tap = 0; tap < 9; tap++) {
            uint32_t abase[2];
            #pragma unroll
            for (int mt = 0; mt < 2; mt++) {
                uint32_t p = (uint32_t)(pb[mt] + TAPOFF[tap]);
                abase[mt] = A + ((p * 64) ^ ((p & 7) << 4));
            }
            uint32_t Bt = B + tap * 2048;
            #pragma unroll
            for (int kk = 0; kk < 2; kk++) {
                uint32_t ksel = ((uint32_t)kk * 2) << 4;
                uint32_t a[2][4];
                #pragma unroll
                for (int mt = 0; mt < 2; mt++)
                    ldsm_x4(a[mt][0], a[mt][1], a[mt][2], a[mt][3],
                            abase[mt] ^ (ksel ^ (aseg << 4)));
                uint32_t b00, b01, b10, b11, b20, b21, b30, b31;
                ldsm_x4(b00, b01, b10, b11, Bt + (bo1 ^ (ksel ^ (bseg << 4))));
                ldsm_x4(b20, b21, b30, b31, Bt + (bo2 ^ (ksel ^ (bseg << 4))));
                #pragma unroll
                for (int mt = 0; mt < 2; mt++) {
                    mma16816(acc[mt][0], a[mt][0], a[mt][1], a[mt][2], a[mt][3], b00, b01);
                    mma16816(acc[mt][1], a[mt][0], a[mt][1], a[mt][2], a[mt][3], b10, b11);
                    mma16816(acc[mt][2], a[mt][0], a[mt][1], a[mt][2], a[mt][3], b20, b21);
                    mma16816(acc[mt][3], a[mt][0], a[mt][1], a[mt][2], a[mt][3], b30, b31);
                }
            }
        }
        __syncthreads();
        if (cg + 2 < 8)
            load_cg(cg + 2, cg & 1, sb, actN, y0, tid);
        asm volatile("cp.async.commit_group;" ::: "memory");
    }

    // ---- epilogue: write channels [256:288] ----
    float* obase = out + ((size_t)n * CTOT + CIN) * HW + y0 * WW;
    int nc = (lane & 3) * 2;
    #pragma unroll
    for (int mt = 0; mt < 2; mt++) {
        int m0 = w * 32 + mt * 16 + (lane >> 2);
        #pragma unroll
        for (int nb = 0; nb < 4; nb++) {
            #pragma unroll
            for (int h = 0; h < 2; h++) {
                int m  = m0 + 8 * h;
                int yy = m >> 6, xx = m & 63;
                if (xx < 56) {
                    float* p = obase + (size_t)(nb * 8 + nc) * HW + yy * WW + xx;
                    p[0]  = acc[mt][nb][2 * h + 0];
                    p[HW] = acc[mt][nb][2 * h + 1];
                }
            }
        }
    }
}

// ---------------- launch (single stream, serial) ----------------
extern "C" void kernel_launch(void* const* d_in, const int* in_sizes, int n_in,
                              void* d_out, int out_size) {
    const float* all_features = (const float*)d_in[0];
    const float* bn_weight    = (const float*)d_in[1];
    const float* bn_bias      = (const float*)d_in[2];
    const float* running_mean = (const float*)d_in[3];
    const float* running_var  = (const float*)d_in[4];
    const float* conv_weight  = (const float*)d_in[5];
    float* out = (float*)d_out;

    static bool attr_set = false;
    if (!attr_set) {
        cudaFuncSetAttribute(conv_kernel,
                             cudaFuncAttributeMaxDynamicSharedMemorySize, CONV_SMEM);
        attr_set = true;
    }

    // stage1 + fused weight transform (cb==4 slice), then conv — one stream.
    dim3 g1(49, 5, NB);
    stage1_kernel<<<g1, 256>>>(all_features, bn_weight, bn_bias,
                               running_mean, running_var, conv_weight, out);

    conv_kernel<<<NB * 14, 256, CONV_SMEM>>>(out);
}

// round 15
// speedup vs baseline: 1.4556x; 1.4556x over previous
#include <cuda_runtime.h>
#include <cuda_fp16.h>
#include <cstdint>

// ---------------- problem constants ----------------
#define NB     32
#define CIN    256
#define COUT   32
#define CTOT   288
#define HH     56
#define WW     56
#define HW     3136
#define EPSV   1e-5f

// activation buffer, channel-group-major:
//   g_act[cg][n][py*58+px][32ch]  fp16, cg in [0,8) covering channels cg*32..+31
// Each (cg,n) plane: 58*58 px x 32ch = 107648 halfs (215.3 KB), fully contiguous
// in pixel order -> conv reads one contiguous slab per cg step.
// __device__ globals are zero-initialized; the pad border is NEVER written,
// so it stays zero across all replays (no border-zero kernel needed).
#define PLANEPITCH (58*58*32)    // halfs per (cg,n) plane

__device__ __half g_act[(size_t)8 * NB * PLANEPITCH];   // 55.1 MB
__device__ __half g_wt[COUT * 2304];                    // [oc][tap*256+c]

// ---------------- PTX helpers (baseline PTX only) ----------------
static __device__ __forceinline__ uint32_t smem_u32(const void* p) {
    uint32_t a;
    asm("{ .reg .u64 t; cvta.to.shared.u64 t, %1; cvt.u32.u64 %0, t; }"
        : "=r"(a) : "l"(p));
    return a;
}
static __device__ __forceinline__ void cp_async16(uint32_t dst, const void* src) {
    asm volatile("cp.async.cg.shared.global [%0], [%1], 16;"
                 :: "r"(dst), "l"(src) : "memory");
}
static __device__ __forceinline__ void ldsm_x4(uint32_t& r0, uint32_t& r1,
                                               uint32_t& r2, uint32_t& r3, uint32_t addr) {
    asm volatile("ldmatrix.sync.aligned.m8n8.x4.shared.b16 {%0,%1,%2,%3}, [%4];"
                 : "=r"(r0), "=r"(r1), "=r"(r2), "=r"(r3) : "r"(addr));
}
static __device__ __forceinline__ void mma16816(float* c, uint32_t a0, uint32_t a1,
                                                uint32_t a2, uint32_t a3,
                                                uint32_t b0, uint32_t b1) {
    asm volatile("mma.sync.aligned.m16n8k16.row.col.f32.f16.f16.f32 "
                 "{%0,%1,%2,%3}, {%4,%5,%6,%7}, {%8,%9}, {%0,%1,%2,%3};"
                 : "+f"(c[0]), "+f"(c[1]), "+f"(c[2]), "+f"(c[3])
                 : "r"(a0), "r"(a1), "r"(a2), "r"(a3), "r"(b0), "r"(b1));
}

// ---------------- kernel 1: weight transform OIHW -> [oc][tap*256+c] fp16 --------
__global__ void wtrans_kernel(const float* __restrict__ w) {
    int j = blockIdx.x * blockDim.x + threadIdx.x;
    if (j < COUT * 2304) {
        int oc = j / 2304;
        int k  = j % 2304;
        int t  = k >> 8;
        int c  = k & 255;
        g_wt[j] = __float2half(w[(oc * CIN + c) * 9 + t]);
    }
}

// ---------------- kernel 2: passthrough + BN+ReLU -> cg-major fp16 planes --------
__global__ __launch_bounds__(256) void stage1_kernel(
    const float* __restrict__ in, const float* __restrict__ bw,
    const float* __restrict__ bb, const float* __restrict__ rm,
    const float* __restrict__ rv, float* __restrict__ out) {
    __shared__ __half st[64][72];     // [pixel][channel-local], 144B pitch
    __shared__ float ss[64], sh[64];

    int pb = blockIdx.x, cb = blockIdx.y, n = blockIdx.z;
    int tid = threadIdx.x;
    if (tid < 64) {
        int c = cb * 64 + tid;
        float s = bw[c] * rsqrtf(rv[c] + EPSV);
        ss[tid] = s;
        sh[tid] = bb[c] - rm[c] * s;
    }
    __syncthreads();

    int ci0 = tid >> 4, pj = tid & 15;
    int p0 = pb * 64;
    #pragma unroll
    for (int r = 0; r < 4; r++) {
        int c = r * 16 + ci0;
        size_t off = ((size_t)n * CTOT + cb * 64 + c) * HW + p0;
        float4 v = ((const float4*)(in + off))[pj];
        ((float4*)(out + off))[pj] = v;                 // passthrough
        float s = ss[c], h = sh[c];
        st[pj * 4 + 0][c] = __float2half(fmaxf(fmaf(v.x, s, h), 0.f));
        st[pj * 4 + 1][c] = __float2half(fmaxf(fmaf(v.y, s, h), 0.f));
        st[pj * 4 + 2][c] = __float2half(fmaxf(fmaf(v.z, s, h), 0.f));
        st[pj * 4 + 3][c] = __float2half(fmaxf(fmaf(v.w, s, h), 0.f));
    }
    __syncthreads();

    // write: seg 0-3 -> plane 2*cb, seg 4-7 -> plane 2*cb+1
    #pragma unroll
    for (int r = 0; r < 2; r++) {
        int e = r * 256 + tid;
        int p = e >> 3, seg = e & 7;
        int P = p0 + p;
        int y = P / 56, x = P % 56;
        int plane = 2 * cb + (seg >> 2);
        uint4 v = *(uint4*)&st[p][seg * 8];
        *(uint4*)(g_act + ((size_t)plane * NB + n) * PLANEPITCH
                  + ((y + 1) * 58 + (x + 1)) * 32 + (seg & 3) * 8) = v;
    }
}

// ---------------- kernel 3: implicit-GEMM conv, tap-reuse in smem ----------------
// (R10 configuration — best measured: M=256 px (4 rows x 64 cols), 8 warps m32n32,
//  2 CTAs/SM). Per cg the A-slab read is one CONTIGUOUS 22.3KB block.
#define ABUF   23040             // 360 px slots x 64B (348 used + read slack)
#define BBUF   18432             // 9 taps x 32 oc x 32 ch x 2B
#define BOFF   (2*ABUF)          // 46080
#define CONV_SMEM (2*ABUF + 2*BBUF)  // 82944

__device__ __constant__ int TAPOFF[9] = {0,1,2, 58,59,60, 116,117,118};

static __device__ __forceinline__ void load_cg(int cg, int buf, uint32_t sb,
                                               int n, int y0, int tid) {
    uint32_t A = sb + buf * ABUF;
    const __half* slab = g_act + ((size_t)cg * NB + n) * PLANEPITCH
                       + (size_t)y0 * 58 * 32;          // contiguous 348 px x 64B
    #pragma unroll
    for (int it = 0; it < 6; it++) {
        int i = tid + it * 256;
        if (i < 1392) {                       // 348 pixels x 4 segs of 16B
            int p = i >> 2, seg = i & 3;
            const void* src = slab + p * 32 + seg * 8;
            uint32_t dst = A + (((uint32_t)p * 64) ^ ((uint32_t)seg << 4)
                                ^ (((uint32_t)(p & 7)) << 4));
            cp_async16(dst, src);
        }
    }
    uint32_t B = sb + BOFF + buf * BBUF;
    #pragma unroll
    for (int it = 0; it < 5; it++) {
        int i = tid + it * 256;
        if (i < 1152) {                       // 9 taps x 32 oc x 4 segs
            int tap = i >> 7, rem = i & 127;
            int oc = rem >> 2, seg = rem & 3;
            const void* src = g_wt + oc * 2304 + tap * 256 + cg * 32 + seg * 8;
            uint32_t dst = B + tap * 2048 + (((uint32_t)oc * 64) ^ ((uint32_t)seg << 4)
                                             ^ (((uint32_t)(oc & 7)) << 4));
            cp_async16(dst, src);
        }
    }
}

__global__ __launch_bounds__(256, 2)
void conv_kernel(float* __restrict__ out) {
    extern __shared__ __align__(128) char smem[];
    uint32_t sb = smem_u32(smem);
    int tid  = threadIdx.x;
    int w    = tid >> 5;                      // warp 0..7 -> m rows [w*32, w*32+32)
    int lane = tid & 31;
    int bx = blockIdx.x;
    int n  = bx / 14;
    int y0 = (bx % 14) * 4;                   // 4 output rows per CTA

    float acc[2][4][4];
    #pragma unroll
    for (int mt = 0; mt < 2; mt++)
        #pragma unroll
        for (int nb = 0; nb < 4; nb++)
            #pragma unroll
            for (int j = 0; j < 4; j++) acc[mt][nb][j] = 0.f;

    // per-lane fragment geometry
    int pb[2];
    #pragma unroll
    for (int mt = 0; mt < 2; mt++) {
        int m  = w * 32 + mt * 16 + (lane & 15);
        int yy = m >> 6, xx = m & 63;
        pb[mt] = yy * 58 + xx;
    }
    uint32_t aseg = (uint32_t)(lane >> 4);              // 0/1: k-half within k16
    int bn1 = ((lane >> 4) & 1) * 8 + (lane & 7);       // B rows n0-15
    int bn2 = bn1 + 16;                                 // B rows n16-31
    uint32_t bsw  = ((uint32_t)(lane & 7)) << 4;
    uint32_t bo1  = ((uint32_t)bn1 * 64) ^ bsw;
    uint32_t bo2  = ((uint32_t)bn2 * 64) ^ bsw;
    uint32_t bseg = (uint32_t)((lane >> 3) & 1);

    // prologue: two cg stages in flight
    load_cg(0, 0, sb, n, y0, tid);
    asm volatile("cp.async.commit_group;" ::: "memory");
    load_cg(1, 1, sb, n, y0, tid);
    asm volatile("cp.async.commit_group;" ::: "memory");

    for (int cg = 0; cg < 8; cg++) {
        asm volatile("cp.async.wait_group 1;" ::: "memory");
        __syncthreads();

        uint32_t A = sb + (cg & 1) * ABUF;
        uint32_t B = sb + BOFF + (cg & 1) * BBUF;

        #pragma unroll
        for (int tap = 0; tap < 9; tap++) {
            uint32_t abase[2];
            #pragma unroll
            for (int mt = 0; mt < 2; mt++) {
                uint32_t p = (uint32_t)(pb[mt] + TAPOFF[tap]);
                abase[mt] = A + ((p * 64) ^ ((p & 7) << 4));
            }
            uint32_t Bt = B + tap * 2048;
            #pragma unroll
            for (int kk = 0; kk < 2; kk++) {
                uint32_t ksel = ((uint32_t)kk * 2) << 4;
                uint32_t a[2][4];
                #pragma unroll
                for (int mt = 0; mt < 2; mt++)
                    ldsm_x4(a[mt][0], a[mt][1], a[mt][2], a[mt][3],
                            abase[mt] ^ (ksel ^ (aseg << 4)));
                uint32_t b00, b01, b10, b11, b20, b21, b30, b31;
                ldsm_x4(b00, b01, b10, b11, Bt + (bo1 ^ (ksel ^ (bseg << 4))));
                ldsm_x4(b20, b21, b30, b31, Bt + (bo2 ^ (ksel ^ (bseg << 4))));
                #pragma unroll
                for (int mt = 0; mt < 2; mt++) {
                    mma16816(acc[mt][0], a[mt][0], a[mt][1], a[mt][2], a[mt][3], b00, b01);
                    mma16816(acc[mt][1], a[mt][0], a[mt][1], a[mt][2], a[mt][3], b10, b11);
                    mma16816(acc[mt][2], a[mt][0], a[mt][1], a[mt][2], a[mt][3], b20, b21);
                    mma16816(acc[mt][3], a[mt][0], a[mt][1], a[mt][2], a[mt][3], b30, b31);
                }
            }
        }
        __syncthreads();
        if (cg + 2 < 8)
            load_cg(cg + 2, cg & 1, sb, n, y0, tid);
        asm volatile("cp.async.commit_group;" ::: "memory");
    }

    // ---- epilogue: write channels [256:288] ----
    float* obase = out + ((size_t)n * CTOT + CIN) * HW + y0 * WW;
    int nc = (lane & 3) * 2;
    #pragma unroll
    for (int mt = 0; mt < 2; mt++) {
        int m0 = w * 32 + mt * 16 + (lane >> 2);
        #pragma unroll
        for (int nb = 0; nb < 4; nb++) {
            #pragma unroll
            for (int h = 0; h < 2; h++) {
                int m  = m0 + 8 * h;
                int yy = m >> 6, xx = m & 63;
                if (xx < 56) {
                    float* p = obase + (size_t)(nb * 8 + nc) * HW + yy * WW + xx;
                    p[0]  = acc[mt][nb][2 * h + 0];
                    p[HW] = acc[mt][nb][2 * h + 1];
                }
            }
        }
    }
}

// ---------------- launch (single stream, serial — R10 structure) ----------------
extern "C" void kernel_launch(void* const* d_in, const int* in_sizes, int n_in,
                              void* d_out, int out_size) {
    const float* all_features = (const float*)d_in[0];
    const float* bn_weight    = (const float*)d_in[1];
    const float* bn_bias      = (const float*)d_in[2];
    const float* running_mean = (const float*)d_in[3];
    const float* running_var  = (const float*)d_in[4];
    const float* conv_weight  = (const float*)d_in[5];
    float* out = (float*)d_out;

    static bool attr_set = false;
    if (!attr_set) {
        cudaFuncSetAttribute(conv_kernel,
                             cudaFuncAttributeMaxDynamicSharedMemorySize, CONV_SMEM);
        attr_set = true;
    }

    wtrans_kernel<<<(COUT * 2304 + 255) / 256, 256>>>(conv_weight);

    dim3 g1(49, 4, NB);   // 64-pixel blocks x 64-channel blocks x images
    stage1_kernel<<<g1, 256>>>(all_features, bn_weight, bn_bias,
                               running_mean, running_var, out);

    conv_kernel<<<NB * 14, 256, CONV_SMEM>>>(out);
}